// round 2
// baseline (speedup 1.0000x reference)
#include <cuda_runtime.h>
#include <math.h>

#define NNODES 30000
#define FIN    500
#define HID    16
#define OUTC   3
#define NEDGE  960000

// ---------------- scratch (static device arrays; no allocation) -------------
__device__ float g_h0  [NNODES * HID];   // after conv stack + max-pool
__device__ float g_lin1[NNODES * HID];   // h0 @ W1
__device__ float g_acc1[NNODES * HID];   // gcn1 aggregation
__device__ float g_lin2[NNODES * 4];     // relu(acc1) @ W2 (padded to 4)
__device__ float g_acc2[NNODES * 4];     // gcn2 aggregation (padded to 4)
__device__ int   g_deg [NNODES];
__device__ float g_dinv[NNODES];

// ---------------- fused conv1 -> relu -> conv2 -> relu -> max ----------------
// one block per node, 512 threads (16 warps). Warp w owns output channel w.
__global__ __launch_bounds__(512, 2)
void conv_max_kernel(const float* __restrict__ x,
                     const float* __restrict__ w1, const float* __restrict__ b1,
                     const float* __restrict__ w2, const float* __restrict__ b2)
{
    __shared__ float xs[512];               // x padded: xs[0]=0, xs[1..500]=x, rest 0
    __shared__ float a_s[HID][512];         // conv1 output, stored[l+1] = a[l], pads = 0
    __shared__ float ws2[HID * HID * 4];    // conv2 weights padded to float4 per (oc,ic)
    __shared__ float ws1[48];
    __shared__ float bs1[16];
    __shared__ float bs2[16];

    const int tid = threadIdx.x;
    const int n   = blockIdx.x;

    // --- phase 0: zero a_s, load x into xs, stage weights --------------------
    {
        float4* a4 = reinterpret_cast<float4*>(&a_s[0][0]);
        #pragma unroll
        for (int i = tid; i < HID * 512 / 4; i += 512)
            a4[i] = make_float4(0.f, 0.f, 0.f, 0.f);

        if (tid < 502)
            xs[tid] = (tid == 0 || tid == 501) ? 0.f : x[n * FIN + (tid - 1)];
        else
            xs[tid] = 0.f;

        for (int i = tid; i < HID * HID * 3; i += 512) {
            int oi = i / 3;
            int t  = i - oi * 3;
            ws2[oi * 4 + t] = w2[i];
        }
        if (tid < 48)                 ws1[tid]      = w1[tid];
        else if (tid < 64)            bs1[tid - 48] = b1[tid - 48];
        else if (tid < 80)            bs2[tid - 64] = b2[tid - 64];
    }
    __syncthreads();

    // --- phase 1: conv1 + relu into a_s (thread p computes all 16 channels) --
    if (tid < FIN) {
        const float xm = xs[tid];
        const float x0 = xs[tid + 1];
        const float xp = xs[tid + 2];
        #pragma unroll
        for (int c = 0; c < HID; c++) {
            float v = bs1[c];
            v = fmaf(ws1[c * 3 + 0], xm, v);
            v = fmaf(ws1[c * 3 + 1], x0, v);
            v = fmaf(ws1[c * 3 + 2], xp, v);
            a_s[c][tid + 1] = fmaxf(v, 0.f);
        }
    }
    __syncthreads();

    // --- phase 2: conv2 + relu + max-pool. warp w -> out channel w. ----------
    {
        const int w    = tid >> 5;
        const int lane = tid & 31;
        const float bias = bs2[w];
        const float4* wrow = reinterpret_cast<const float4*>(&ws2[w * 64]);

        float mmax = -1e30f;
        #pragma unroll
        for (int it = 0; it < 4; it++) {
            const int p = it * 128 + lane * 4;   // positions p..p+3 (p % 4 == 0)
            if (p < FIN) {                        // p <= 496 -> all 4 positions valid
                float a0 = bias, a1 = bias, a2 = bias, a3 = bias;
                #pragma unroll
                for (int ic = 0; ic < HID; ic++) {
                    const float4 wv = wrow[ic];                                   // taps 0..2
                    const float4 av = *reinterpret_cast<const float4*>(&a_s[ic][p]);     // a[p-1..p+2]
                    const float2 bv = *reinterpret_cast<const float2*>(&a_s[ic][p + 4]); // a[p+3..p+4]
                    a0 = fmaf(wv.x, av.x, a0); a0 = fmaf(wv.y, av.y, a0); a0 = fmaf(wv.z, av.z, a0);
                    a1 = fmaf(wv.x, av.y, a1); a1 = fmaf(wv.y, av.z, a1); a1 = fmaf(wv.z, av.w, a1);
                    a2 = fmaf(wv.x, av.z, a2); a2 = fmaf(wv.y, av.w, a2); a2 = fmaf(wv.z, bv.x, a2);
                    a3 = fmaf(wv.x, av.w, a3); a3 = fmaf(wv.y, bv.x, a3); a3 = fmaf(wv.z, bv.y, a3);
                }
                mmax = fmaxf(mmax, fmaxf(fmaxf(a0, a1), fmaxf(a2, a3)));
            }
        }
        #pragma unroll
        for (int off = 16; off; off >>= 1)
            mmax = fmaxf(mmax, __shfl_xor_sync(0xffffffffu, mmax, off));
        if (lane == 0)
            g_h0[n * HID + w] = fmaxf(mmax, 0.f);   // max of relu == relu of max
    }
}

// ---------------- degree ------------------------------------------------------
__global__ void deg_zero_kernel()
{
    int i = blockIdx.x * blockDim.x + threadIdx.x;
    if (i < NNODES) g_deg[i] = 0;
}

__global__ void deg_count_kernel(const int* __restrict__ dst)
{
    int i = blockIdx.x * blockDim.x + threadIdx.x;
    if (i < NEDGE) atomicAdd(&g_deg[dst[i]], 1);
}

__global__ void dinv_kernel()
{
    int i = blockIdx.x * blockDim.x + threadIdx.x;
    if (i < NNODES) g_dinv[i] = rsqrtf((float)(g_deg[i] + 1));  // +1 self loop
}

// ---------------- gcn1: linear + self-loop init ------------------------------
__global__ void lin1_kernel(const float* __restrict__ W, const float* __restrict__ b)
{
    __shared__ float Ws[HID * HID];
    __shared__ float bs[HID];
    const int tid = threadIdx.x;
    if (tid < HID * HID) Ws[tid] = W[tid];
    if (tid < HID)       bs[tid] = b[tid];
    __syncthreads();

    const int i = blockIdx.x * blockDim.x + tid;
    if (i >= NNODES) return;

    float h[HID];
    const float4* hp = reinterpret_cast<const float4*>(&g_h0[i * HID]);
    #pragma unroll
    for (int q = 0; q < 4; q++) {
        float4 v = hp[q];
        h[q * 4 + 0] = v.x; h[q * 4 + 1] = v.y; h[q * 4 + 2] = v.z; h[q * 4 + 3] = v.w;
    }
    float acc[HID];
    #pragma unroll
    for (int c = 0; c < HID; c++) acc[c] = 0.f;
    #pragma unroll
    for (int in = 0; in < HID; in++) {
        const float hv = h[in];
        #pragma unroll
        for (int c = 0; c < HID; c++) acc[c] = fmaf(hv, Ws[in * HID + c], acc[c]);
    }
    const float di = g_dinv[i];
    const float d2 = di * di;
    #pragma unroll
    for (int c = 0; c < HID; c++) {
        g_lin1[i * HID + c] = acc[c];
        g_acc1[i * HID + c] = fmaf(d2, acc[c], bs[c]);  // self loop + bias
    }
}

// ---------------- gcn1: edge scatter (4 threads per edge, float4 each) -------
__global__ void scatter1_kernel(const int* __restrict__ src, const int* __restrict__ dst)
{
    int idx = blockIdx.x * blockDim.x + threadIdx.x;
    if (idx >= NEDGE * 4) return;
    const int e = idx >> 2;
    const int q = idx & 3;
    const int s = src[e];
    const int d = dst[e];
    const float w = g_dinv[s] * g_dinv[d];
    const float4 v = reinterpret_cast<const float4*>(&g_lin1[s * HID])[q];
    float* out = &g_acc1[d * HID + q * 4];
    atomicAdd(out + 0, w * v.x);
    atomicAdd(out + 1, w * v.y);
    atomicAdd(out + 2, w * v.z);
    atomicAdd(out + 3, w * v.w);
}

// ---------------- gcn2: relu + linear(16->3) + self-loop init ----------------
__global__ void lin2_kernel(const float* __restrict__ W, const float* __restrict__ b)
{
    __shared__ float Ws[HID * OUTC];
    __shared__ float bs[OUTC];
    const int tid = threadIdx.x;
    if (tid < HID * OUTC) Ws[tid] = W[tid];
    if (tid < OUTC)       bs[tid] = b[tid];
    __syncthreads();

    const int i = blockIdx.x * blockDim.x + tid;
    if (i >= NNODES) return;

    float h[HID];
    const float4* hp = reinterpret_cast<const float4*>(&g_acc1[i * HID]);
    #pragma unroll
    for (int q = 0; q < 4; q++) {
        float4 v = hp[q];
        h[q * 4 + 0] = fmaxf(v.x, 0.f); h[q * 4 + 1] = fmaxf(v.y, 0.f);
        h[q * 4 + 2] = fmaxf(v.z, 0.f); h[q * 4 + 3] = fmaxf(v.w, 0.f);
    }
    float acc[OUTC] = {0.f, 0.f, 0.f};
    #pragma unroll
    for (int in = 0; in < HID; in++) {
        const float hv = h[in];
        #pragma unroll
        for (int c = 0; c < OUTC; c++) acc[c] = fmaf(hv, Ws[in * OUTC + c], acc[c]);
    }
    const float di = g_dinv[i];
    const float d2 = di * di;
    #pragma unroll
    for (int c = 0; c < OUTC; c++) {
        g_lin2[i * 4 + c] = acc[c];
        g_acc2[i * 4 + c] = fmaf(d2, acc[c], bs[c]);
    }
    g_lin2[i * 4 + 3] = 0.f;
    g_acc2[i * 4 + 3] = 0.f;
}

// ---------------- gcn2: edge scatter (1 thread per edge, 3 channels) ---------
__global__ void scatter2_kernel(const int* __restrict__ src, const int* __restrict__ dst)
{
    int e = blockIdx.x * blockDim.x + threadIdx.x;
    if (e >= NEDGE) return;
    const int s = src[e];
    const int d = dst[e];
    const float w = g_dinv[s] * g_dinv[d];
    const float4 v = *reinterpret_cast<const float4*>(&g_lin2[s * 4]);
    float* out = &g_acc2[d * 4];
    atomicAdd(out + 0, w * v.x);
    atomicAdd(out + 1, w * v.y);
    atomicAdd(out + 2, w * v.z);
}

// ---------------- log_softmax ------------------------------------------------
__global__ void logsoftmax_kernel(float* __restrict__ out)
{
    int i = blockIdx.x * blockDim.x + threadIdx.x;
    if (i >= NNODES) return;
    const float z0 = g_acc2[i * 4 + 0];
    const float z1 = g_acc2[i * 4 + 1];
    const float z2 = g_acc2[i * 4 + 2];
    const float m  = fmaxf(z0, fmaxf(z1, z2));
    const float s  = expf(z0 - m) + expf(z1 - m) + expf(z2 - m);
    const float l  = m + logf(s);
    out[i * 3 + 0] = z0 - l;
    out[i * 3 + 1] = z1 - l;
    out[i * 3 + 2] = z2 - l;
}

// ---------------- launcher ---------------------------------------------------
extern "C" void kernel_launch(void* const* d_in, const int* in_sizes, int n_in,
                              void* d_out, int out_size)
{
    const float* x       = (const float*)d_in[0];
    const float* conv1_w = (const float*)d_in[1];
    const float* conv1_b = (const float*)d_in[2];
    const float* conv2_w = (const float*)d_in[3];
    const float* conv2_b = (const float*)d_in[4];
    const float* gcn1_w  = (const float*)d_in[5];
    const float* gcn1_b  = (const float*)d_in[6];
    const float* gcn2_w  = (const float*)d_in[7];
    const float* gcn2_b  = (const float*)d_in[8];
    const int*   edges   = (const int*)d_in[9];   // (2, E): row0 src, row1 dst
    const int*   src     = edges;
    const int*   dst     = edges + NEDGE;
    float*       out     = (float*)d_out;

    conv_max_kernel<<<NNODES, 512>>>(x, conv1_w, conv1_b, conv2_w, conv2_b);

    deg_zero_kernel <<<(NNODES + 255) / 256, 256>>>();
    deg_count_kernel<<<(NEDGE + 255) / 256, 256>>>(dst);
    dinv_kernel     <<<(NNODES + 255) / 256, 256>>>();

    lin1_kernel   <<<(NNODES + 255) / 256, 256>>>(gcn1_w, gcn1_b);
    scatter1_kernel<<<(NEDGE * 4 + 255) / 256, 256>>>(src, dst);

    lin2_kernel   <<<(NNODES + 255) / 256, 256>>>(gcn2_w, gcn2_b);
    scatter2_kernel<<<(NEDGE + 255) / 256, 256>>>(src, dst);

    logsoftmax_kernel<<<(NNODES + 255) / 256, 256>>>(out);
}

// round 4
// speedup vs baseline: 1.6804x; 1.6804x over previous
#include <cuda_runtime.h>
#include <math.h>

#define NNODES 30000
#define FIN    500
#define HID    16
#define OUTC   3
#define NEDGE  960000

// ---------------- scratch (static device arrays; no allocation) -------------
__device__ float g_h0  [NNODES * HID];   // after conv stack + max-pool
__device__ float g_lin1[NNODES * HID];   // h0 @ W1
__device__ float g_acc1[NNODES * HID];   // gcn1 aggregation
__device__ float g_lin2[NNODES * 4];     // relu(acc1) @ W2 (padded to 4)
__device__ float g_acc2[NNODES * 4];     // gcn2 aggregation (padded to 4)
__device__ int   g_deg [NNODES];
__device__ float g_dinv[NNODES];

// ---------------- f32x2 packed-FMA helpers (sm_103a FFMA2) ------------------
__device__ __forceinline__ unsigned long long fma2(unsigned long long a,
                                                   unsigned long long b,
                                                   unsigned long long c)
{
    unsigned long long d;
    asm("fma.rn.f32x2 %0, %1, %2, %3;" : "=l"(d) : "l"(a), "l"(b), "l"(c));
    return d;
}
__device__ __forceinline__ unsigned long long dup2(float x)
{
    unsigned long long d;
    asm("mov.b64 %0, {%1, %1};" : "=l"(d) : "f"(x));
    return d;
}
__device__ __forceinline__ float2 unpk(unsigned long long v)
{
    float2 r;
    asm("mov.b64 {%0, %1}, %2;" : "=f"(r.x), "=f"(r.y) : "l"(v));
    return r;
}

// ---------------- fused conv1 -> relu -> conv2 -> relu -> max ----------------
// one block per node, 512 threads.
// Phase 2 layout: tid = g*128 + pg ; g = oc-group (4 oc), pg = position group (4 pos).
__global__ __launch_bounds__(512, 2)
void conv_max_kernel(const float* __restrict__ x,
                     const float* __restrict__ w1, const float* __restrict__ b1,
                     const float* __restrict__ w2, const float* __restrict__ b2)
{
    __shared__ float xs[512];                      // x padded: xs[0]=0, xs[1..500]=x
    __shared__ float a_s[HID][512];                // conv1 out, [l+1] = a[l], pads 0
    __shared__ __align__(16) float ws2p[HID*3*16]; // transposed w2: [ic][tap][oc]
    __shared__ float ws1[48];
    __shared__ float bs1[16];
    __shared__ __align__(16) float bs2[16];
    __shared__ float red[4][16];

    const int tid = threadIdx.x;
    const int n   = blockIdx.x;

    // --- phase 0: zero a_s, load x, stage weights ----------------------------
    {
        float4* a4 = reinterpret_cast<float4*>(&a_s[0][0]);
        #pragma unroll
        for (int i = tid; i < HID * 512 / 4; i += 512)
            a4[i] = make_float4(0.f, 0.f, 0.f, 0.f);

        if (tid < 502)
            xs[tid] = (tid == 0 || tid == 501) ? 0.f : x[n * FIN + (tid - 1)];
        else
            xs[tid] = 0.f;

        // ws2p[(ic*3 + t)*16 + oc] = w2[oc*48 + ic*3 + t]
        for (int i = tid; i < HID * 3 * HID; i += 512) {
            int ic  = i / 48;
            int rem = i - ic * 48;
            int t   = rem >> 4;
            int oc  = rem & 15;
            ws2p[i] = w2[oc * 48 + ic * 3 + t];
        }
        if (tid < 48)                 ws1[tid]      = w1[tid];
        else if (tid < 64)            bs1[tid - 48] = b1[tid - 48];
        else if (tid < 80)            bs2[tid - 64] = b2[tid - 64];
    }
    __syncthreads();

    // --- phase 1: conv1 + relu into a_s --------------------------------------
    if (tid < FIN) {
        const float xm = xs[tid];
        const float x0 = xs[tid + 1];
        const float xp = xs[tid + 2];
        #pragma unroll
        for (int c = 0; c < HID; c++) {
            float v = bs1[c];
            v = fmaf(ws1[c * 3 + 0], xm, v);
            v = fmaf(ws1[c * 3 + 1], x0, v);
            v = fmaf(ws1[c * 3 + 2], xp, v);
            a_s[c][tid + 1] = fmaxf(v, 0.f);
        }
    }
    __syncthreads();

    // --- phase 2: conv2 (FFMA2 packed over oc-pairs) + relu + max ------------
    {
        const int g  = tid >> 7;     // oc group: channels 4g .. 4g+3
        const int pg = tid & 127;    // position group: positions 4pg .. 4pg+3
        float mx0 = -1e30f, mx1 = -1e30f, mx2 = -1e30f, mx3 = -1e30f;

        if (pg < 125) {              // p0 <= 496 -> all 4 positions valid
            const int p0 = pg << 2;
            const unsigned long long b01 = *reinterpret_cast<const unsigned long long*>(&bs2[4 * g]);
            const unsigned long long b23 = *reinterpret_cast<const unsigned long long*>(&bs2[4 * g + 2]);
            unsigned long long acc[4][2];
            #pragma unroll
            for (int r = 0; r < 4; r++) { acc[r][0] = b01; acc[r][1] = b23; }

            #pragma unroll
            for (int ic = 0; ic < HID; ic++) {
                const float4 av0 = *reinterpret_cast<const float4*>(&a_s[ic][p0]);
                const float2 av1 = *reinterpret_cast<const float2*>(&a_s[ic][p0 + 4]);
                unsigned long long d[6];
                d[0] = dup2(av0.x); d[1] = dup2(av0.y); d[2] = dup2(av0.z);
                d[3] = dup2(av0.w); d[4] = dup2(av1.x); d[5] = dup2(av1.y);

                const ulonglong2 w0 = *reinterpret_cast<const ulonglong2*>(&ws2p[(ic * 3 + 0) * 16 + 4 * g]);
                const ulonglong2 w1v = *reinterpret_cast<const ulonglong2*>(&ws2p[(ic * 3 + 1) * 16 + 4 * g]);
                const ulonglong2 w2v = *reinterpret_cast<const ulonglong2*>(&ws2p[(ic * 3 + 2) * 16 + 4 * g]);

                #pragma unroll
                for (int r = 0; r < 4; r++) {
                    acc[r][0] = fma2(w0.x,  d[r],     acc[r][0]);
                    acc[r][1] = fma2(w0.y,  d[r],     acc[r][1]);
                    acc[r][0] = fma2(w1v.x, d[r + 1], acc[r][0]);
                    acc[r][1] = fma2(w1v.y, d[r + 1], acc[r][1]);
                    acc[r][0] = fma2(w2v.x, d[r + 2], acc[r][0]);
                    acc[r][1] = fma2(w2v.y, d[r + 2], acc[r][1]);
                }
            }
            #pragma unroll
            for (int r = 0; r < 4; r++) {
                const float2 u0 = unpk(acc[r][0]);
                const float2 u1 = unpk(acc[r][1]);
                mx0 = fmaxf(mx0, u0.x); mx1 = fmaxf(mx1, u0.y);
                mx2 = fmaxf(mx2, u1.x); mx3 = fmaxf(mx3, u1.y);
            }
        }
        // warp reduce (all lanes in a warp share the same oc group)
        #pragma unroll
        for (int off = 16; off; off >>= 1) {
            mx0 = fmaxf(mx0, __shfl_xor_sync(0xffffffffu, mx0, off));
            mx1 = fmaxf(mx1, __shfl_xor_sync(0xffffffffu, mx1, off));
            mx2 = fmaxf(mx2, __shfl_xor_sync(0xffffffffu, mx2, off));
            mx3 = fmaxf(mx3, __shfl_xor_sync(0xffffffffu, mx3, off));
        }
        const int lane = tid & 31;
        const int wig  = (tid >> 5) & 3;   // warp index within oc group
        if (lane == 0) {
            red[wig][4 * g + 0] = mx0;
            red[wig][4 * g + 1] = mx1;
            red[wig][4 * g + 2] = mx2;
            red[wig][4 * g + 3] = mx3;
        }
        __syncthreads();
        if (tid < HID) {
            float m = fmaxf(fmaxf(red[0][tid], red[1][tid]),
                            fmaxf(red[2][tid], red[3][tid]));
            g_h0[n * HID + tid] = fmaxf(m, 0.f);   // relu(max) == max(relu)
        }
    }
}

// ---------------- degree ------------------------------------------------------
__global__ void deg_zero_kernel()
{
    int i = blockIdx.x * blockDim.x + threadIdx.x;
    if (i < NNODES) g_deg[i] = 0;
}

__global__ void deg_count_kernel(const int* __restrict__ dst)
{
    int i = blockIdx.x * blockDim.x + threadIdx.x;
    if (i < NEDGE) atomicAdd(&g_deg[dst[i]], 1);
}

__global__ void dinv_kernel()
{
    int i = blockIdx.x * blockDim.x + threadIdx.x;
    if (i < NNODES) g_dinv[i] = rsqrtf((float)(g_deg[i] + 1));  // +1 self loop
}

// ---------------- gcn1: linear + self-loop init ------------------------------
__global__ void lin1_kernel(const float* __restrict__ W, const float* __restrict__ b)
{
    __shared__ float Ws[HID * HID];
    __shared__ float bs[HID];
    const int tid = threadIdx.x;
    if (tid < HID * HID) Ws[tid] = W[tid];
    if (tid < HID)       bs[tid] = b[tid];
    __syncthreads();

    const int i = blockIdx.x * blockDim.x + tid;
    if (i >= NNODES) return;

    float h[HID];
    const float4* hp = reinterpret_cast<const float4*>(&g_h0[i * HID]);
    #pragma unroll
    for (int q = 0; q < 4; q++) {
        float4 v = hp[q];
        h[q * 4 + 0] = v.x; h[q * 4 + 1] = v.y; h[q * 4 + 2] = v.z; h[q * 4 + 3] = v.w;
    }
    float acc[HID];
    #pragma unroll
    for (int c = 0; c < HID; c++) acc[c] = 0.f;
    #pragma unroll
    for (int in = 0; in < HID; in++) {
        const float hv = h[in];
        #pragma unroll
        for (int c = 0; c < HID; c++) acc[c] = fmaf(hv, Ws[in * HID + c], acc[c]);
    }
    const float di = g_dinv[i];
    const float d2 = di * di;
    #pragma unroll
    for (int c = 0; c < HID; c++) {
        g_lin1[i * HID + c] = acc[c];
        g_acc1[i * HID + c] = fmaf(d2, acc[c], bs[c]);  // self loop + bias
    }
}

// ---------------- gcn1: edge scatter (4 threads per edge, float4 each) -------
__global__ void scatter1_kernel(const int* __restrict__ src, const int* __restrict__ dst)
{
    int idx = blockIdx.x * blockDim.x + threadIdx.x;
    if (idx >= NEDGE * 4) return;
    const int e = idx >> 2;
    const int q = idx & 3;
    const int s = src[e];
    const int d = dst[e];
    const float w = g_dinv[s] * g_dinv[d];
    const float4 v = reinterpret_cast<const float4*>(&g_lin1[s * HID])[q];
    float* out = &g_acc1[d * HID + q * 4];
    atomicAdd(out + 0, w * v.x);
    atomicAdd(out + 1, w * v.y);
    atomicAdd(out + 2, w * v.z);
    atomicAdd(out + 3, w * v.w);
}

// ---------------- gcn2: relu + linear(16->3) + self-loop init ----------------
__global__ void lin2_kernel(const float* __restrict__ W, const float* __restrict__ b)
{
    __shared__ float Ws[HID * OUTC];
    __shared__ float bs[OUTC];
    const int tid = threadIdx.x;
    if (tid < HID * OUTC) Ws[tid] = W[tid];
    if (tid < OUTC)       bs[tid] = b[tid];
    __syncthreads();

    const int i = blockIdx.x * blockDim.x + tid;
    if (i >= NNODES) return;

    float h[HID];
    const float4* hp = reinterpret_cast<const float4*>(&g_acc1[i * HID]);
    #pragma unroll
    for (int q = 0; q < 4; q++) {
        float4 v = hp[q];
        h[q * 4 + 0] = fmaxf(v.x, 0.f); h[q * 4 + 1] = fmaxf(v.y, 0.f);
        h[q * 4 + 2] = fmaxf(v.z, 0.f); h[q * 4 + 3] = fmaxf(v.w, 0.f);
    }
    float acc[OUTC] = {0.f, 0.f, 0.f};
    #pragma unroll
    for (int in = 0; in < HID; in++) {
        const float hv = h[in];
        #pragma unroll
        for (int c = 0; c < OUTC; c++) acc[c] = fmaf(hv, Ws[in * OUTC + c], acc[c]);
    }
    const float di = g_dinv[i];
    const float d2 = di * di;
    #pragma unroll
    for (int c = 0; c < OUTC; c++) {
        g_lin2[i * 4 + c] = acc[c];
        g_acc2[i * 4 + c] = fmaf(d2, acc[c], bs[c]);
    }
    g_lin2[i * 4 + 3] = 0.f;
    g_acc2[i * 4 + 3] = 0.f;
}

// ---------------- gcn2: edge scatter (1 thread per edge, 3 channels) ---------
__global__ void scatter2_kernel(const int* __restrict__ src, const int* __restrict__ dst)
{
    int e = blockIdx.x * blockDim.x + threadIdx.x;
    if (e >= NEDGE) return;
    const int s = src[e];
    const int d = dst[e];
    const float w = g_dinv[s] * g_dinv[d];
    const float4 v = *reinterpret_cast<const float4*>(&g_lin2[s * 4]);
    float* out = &g_acc2[d * 4];
    atomicAdd(out + 0, w * v.x);
    atomicAdd(out + 1, w * v.y);
    atomicAdd(out + 2, w * v.z);
}

// ---------------- log_softmax ------------------------------------------------
__global__ void logsoftmax_kernel(float* __restrict__ out)
{
    int i = blockIdx.x * blockDim.x + threadIdx.x;
    if (i >= NNODES) return;
    const float z0 = g_acc2[i * 4 + 0];
    const float z1 = g_acc2[i * 4 + 1];
    const float z2 = g_acc2[i * 4 + 2];
    const float m  = fmaxf(z0, fmaxf(z1, z2));
    const float s  = expf(z0 - m) + expf(z1 - m) + expf(z2 - m);
    const float l  = m + logf(s);
    out[i * 3 + 0] = z0 - l;
    out[i * 3 + 1] = z1 - l;
    out[i * 3 + 2] = z2 - l;
}

// ---------------- launcher ---------------------------------------------------
extern "C" void kernel_launch(void* const* d_in, const int* in_sizes, int n_in,
                              void* d_out, int out_size)
{
    const float* x       = (const float*)d_in[0];
    const float* conv1_w = (const float*)d_in[1];
    const float* conv1_b = (const float*)d_in[2];
    const float* conv2_w = (const float*)d_in[3];
    const float* conv2_b = (const float*)d_in[4];
    const float* gcn1_w  = (const float*)d_in[5];
    const float* gcn1_b  = (const float*)d_in[6];
    const float* gcn2_w  = (const float*)d_in[7];
    const float* gcn2_b  = (const float*)d_in[8];
    const int*   edges   = (const int*)d_in[9];   // (2, E): row0 src, row1 dst
    const int*   src     = edges;
    const int*   dst     = edges + NEDGE;
    float*       out     = (float*)d_out;

    conv_max_kernel<<<NNODES, 512>>>(x, conv1_w, conv1_b, conv2_w, conv2_b);

    deg_zero_kernel <<<(NNODES + 255) / 256, 256>>>();
    deg_count_kernel<<<(NEDGE + 255) / 256, 256>>>(dst);
    dinv_kernel     <<<(NNODES + 255) / 256, 256>>>();

    lin1_kernel   <<<(NNODES + 255) / 256, 256>>>(gcn1_w, gcn1_b);
    scatter1_kernel<<<(NEDGE * 4 + 255) / 256, 256>>>(src, dst);

    lin2_kernel   <<<(NNODES + 255) / 256, 256>>>(gcn2_w, gcn2_b);
    scatter2_kernel<<<(NEDGE + 255) / 256, 256>>>(src, dst);

    logsoftmax_kernel<<<(NNODES + 255) / 256, 256>>>(out);
}